// round 11
// baseline (speedup 1.0000x reference)
#include <cuda_runtime.h>

#define BB   64
#define TT   512
#define HH   1024
#define CC   8
#define NROW 32768
#define LOGITS_OFF 1
#define PRED_OFF   (1 + 3*BB*TT*CC)
#define FULLM 0xFFFFFFFFu

__device__ float g_expo[3 * NROW * CC];   // exp(logits)

__device__ __forceinline__ void ffma2(unsigned long long& d,
                                      unsigned long long a,
                                      unsigned long long b) {
    asm("fma.rn.f32x2 %0, %1, %2, %0;" : "+l"(d) : "l"(a), "l"(b));
}
__device__ __forceinline__ void cpa16(unsigned sm, const void* g) {
    asm volatile("cp.async.cg.shared.global [%0], [%1], 16;" :: "r"(sm), "l"(g));
}

// ---------------------------------------------------------------------------
// GEMM: M=32768, N=24, K=1024. 256 blocks x 128 threads (4 warps).
// Warps 0-1 -> cols 0-11, warps 2-3 -> cols 12-23 (whole warp same cols =>
// W LDS broadcast). Thread = rows {rowid, rowid+64} x 12 cols, f32x2 FMA.
// ---------------------------------------------------------------------------
__global__ __launch_bounds__(128) void gemm_kernel(
    const float* __restrict__ enc, const float* __restrict__ W,
    const float* __restrict__ bias, float* __restrict__ out)
{
    __shared__ float As[2][128 * 20];
    __shared__ float Ws[2][24 * 20];

    const int tid   = threadIdx.x;
    const int wid   = tid >> 5;
    const int lane  = tid & 31;
    const int rb    = blockIdx.x * 128;
    const int cg    = wid >> 1;               // col group 0/1
    const int c0    = cg * 12;
    const int rowid = (wid & 1) * 32 + lane;  // 0..63; rows rowid, rowid+64
    if (blockIdx.x == 0 && tid == 0) out[0] = 0.0f;

    unsigned long long acc[2][12];
    #pragma unroll
    for (int h = 0; h < 2; h++)
        #pragma unroll
        for (int m = 0; m < 12; m++) acc[h][m] = 0ull;

    unsigned asB[2] = { (unsigned)__cvta_generic_to_shared(&As[0][0]),
                        (unsigned)__cvta_generic_to_shared(&As[1][0]) };
    unsigned wsB[2] = { (unsigned)__cvta_generic_to_shared(&Ws[0][0]),
                        (unsigned)__cvta_generic_to_shared(&Ws[1][0]) };

    auto load_tiles = [&](int kb, int bf) {
        #pragma unroll
        for (int i = 0; i < 4; i++) {
            int idx = tid + i * 128;
            int row = idx >> 2, q = idx & 3;
            cpa16(asB[bf] + (row * 20 + q * 4) * 4,
                  enc + (size_t)(rb + row) * HH + kb + q * 4);
        }
        if (tid < 96) {
            int c = tid >> 2, q = tid & 3;
            cpa16(wsB[bf] + (c * 20 + q * 4) * 4, W + (size_t)c * HH + kb + q * 4);
        }
        asm volatile("cp.async.commit_group;");
    };

    load_tiles(0, 0);
    int buf = 0;
    for (int kb = 0; kb < HH; kb += 16, buf ^= 1) {
        if (kb + 16 < HH) {
            load_tiles(kb + 16, buf ^ 1);
            asm volatile("cp.async.wait_group 1;");
        } else {
            asm volatile("cp.async.wait_group 0;");
        }
        __syncthreads();
        #pragma unroll
        for (int k4 = 0; k4 < 16; k4 += 4) {
            ulonglong2 a0 = *reinterpret_cast<const ulonglong2*>(&As[buf][rowid * 20 + k4]);
            ulonglong2 a1 = *reinterpret_cast<const ulonglong2*>(&As[buf][(rowid + 64) * 20 + k4]);
            #pragma unroll
            for (int m = 0; m < 12; m++) {
                ulonglong2 wv = *reinterpret_cast<const ulonglong2*>(&Ws[buf][(c0 + m) * 20 + k4]);
                ffma2(acc[0][m], a0.x, wv.x);
                ffma2(acc[0][m], a0.y, wv.y);
                ffma2(acc[1][m], a1.x, wv.x);
                ffma2(acc[1][m], a1.y, wv.y);
            }
        }
        __syncthreads();
    }

    #pragma unroll
    for (int h = 0; h < 2; h++) {
        const int r = rb + rowid + 64 * h;
        #pragma unroll
        for (int m = 0; m < 12; m++) {
            int col = c0 + m;
            int kt = col >> 3, cc = col & 7;
            float2 f = *reinterpret_cast<float2*>(&acc[h][m]);
            float val = f.x + f.y + bias[col];
            size_t base = ((size_t)kt * NROW + r) * 8 + cc;
            out[LOGITS_OFF + base] = val;
            g_expo[base] = __expf(val);
        }
    }
}

// ---------------------------------------------------------------------------
// crf: 192 blocks x 144 threads, 2 sequences per block.
// Blocks 0..95   : Viterbi chain (warp0, lanes 0-15; others parked) + decode.
// Blocks 96..191 : forward chunk matrices + numerator + logZ + loss.
// ---------------------------------------------------------------------------
__global__ __launch_bounds__(144) void crf_kernel(
    const int* __restrict__ labels, const float* __restrict__ start_t,
    const float* __restrict__ end_t, const float* __restrict__ trans,
    float* __restrict__ out)
{
    __shared__ float         vsm[2][TT][8];        // 32KB
    __shared__ unsigned char path[2][8][8][64];    // 8KB
    __shared__ unsigned char sel[2][8];
    __shared__ float         strT[64];             // strT[tag*8+i] = trans[i*8+tag]
    __shared__ int           lastsh[2];
    __shared__ float         Psm[2][8][8][8];      // matrix blocks: [sl][chunk][ib][j]
    __shared__ float         numsh[2];

    const int tid  = threadIdx.x;
    const int lane = tid & 31;

    if (blockIdx.x < 96) {
        // =================== chain + decode block ===================
        const int s0 = blockIdx.x * 2;
        const int kt = s0 >> 6;

        if (tid < 64) strT[tid] = trans[kt * 64 + (tid & 7) * 8 + (tid >> 3)];

        if (tid < 32 && lane < 16) {
            // ---- exact Viterbi chain: lanes 0-7 seq0, 8-15 seq1 ----
            const int sl = lane >> 3, j = lane & 7;
            const int s  = s0 + sl;
            const float* em = out + LOGITS_OFF + (size_t)s * (TT * CC);

            float tr[8];
            #pragma unroll
            for (int i = 0; i < 8; i++) tr[i] = trans[kt * 64 + i * 8 + j];

            float v = start_t[kt * 8 + j] + em[j];
            vsm[sl][0][j] = v;

            float eb[8];
            #pragma unroll
            for (int u = 0; u < 8; u++) eb[u] = em[(1 + u) * 8 + j];

            for (int tw = 1; tw < TT; tw += 8) {
                float nb[8];
                #pragma unroll
                for (int u = 0; u < 8; u++) {
                    int tn = tw + 8 + u;
                    nb[u] = (tn < TT) ? em[tn * 8 + j] : 0.0f;
                }
                #pragma unroll
                for (int u = 0; u < 8; u++) {
                    int t = tw + u;
                    if (t < TT) {
                        float c0 = __shfl_sync(0xFFFFu, v, 0, 8) + tr[0];
                        float c1 = __shfl_sync(0xFFFFu, v, 1, 8) + tr[1];
                        float c2 = __shfl_sync(0xFFFFu, v, 2, 8) + tr[2];
                        float c3 = __shfl_sync(0xFFFFu, v, 3, 8) + tr[3];
                        float c4 = __shfl_sync(0xFFFFu, v, 4, 8) + tr[4];
                        float c5 = __shfl_sync(0xFFFFu, v, 5, 8) + tr[5];
                        float c6 = __shfl_sync(0xFFFFu, v, 6, 8) + tr[6];
                        float c7 = __shfl_sync(0xFFFFu, v, 7, 8) + tr[7];
                        float m = fmaxf(fmaxf(fmaxf(c0, c1), fmaxf(c2, c3)),
                                        fmaxf(fmaxf(c4, c5), fmaxf(c6, c7)));
                        v = m + eb[u];
                        vsm[sl][t][j] = v;
                    }
                }
                #pragma unroll
                for (int u = 0; u < 8; u++) eb[u] = nb[u];
            }

            float y = v + end_t[kt * 8 + j];
            float g[8];
            #pragma unroll
            for (int i = 0; i < 8; i++) g[i] = __shfl_sync(0xFFFFu, y, i, 8);
            float bv = g[0]; int last = 0;
            #pragma unroll
            for (int i = 1; i < 8; i++) { if (g[i] > bv) { bv = g[i]; last = i; } }
            if (j == 0) lastsh[sl] = last;
        }
        __syncthreads();

        if (tid < 128) {
            // ---- decode: per (seq, chunk, hypothesis) backtrace ----
            const int local = tid >> 6;
            const int lt    = tid & 63;
            const int c  = lt >> 3, h = lt & 7;
            const int tb = c * 64 + 1;
            const int te = (c * 64 + 64 < TT) ? c * 64 + 64 : TT - 1;
            int tag = h;
            for (int t = te; t >= tb; t--) {
                float4 va = *reinterpret_cast<const float4*>(&vsm[local][t - 1][0]);
                float4 vb = *reinterpret_cast<const float4*>(&vsm[local][t - 1][4]);
                const float* tc = &strT[tag * 8];
                float c0 = va.x + tc[0], c1 = va.y + tc[1];
                float c2 = va.z + tc[2], c3 = va.w + tc[3];
                float c4 = vb.x + tc[4], c5 = vb.y + tc[5];
                float c6 = vb.z + tc[6], c7 = vb.w + tc[7];
                float m = fmaxf(fmaxf(fmaxf(c0, c1), fmaxf(c2, c3)),
                                fmaxf(fmaxf(c4, c5), fmaxf(c6, c7)));
                unsigned mk = (c0 == m) ? 1u : 0u;
                mk |= (c1 == m) ? 2u : 0u;
                mk |= (c2 == m) ? 4u : 0u;
                mk |= (c3 == m) ? 8u : 0u;
                mk |= (c4 == m) ? 16u : 0u;
                mk |= (c5 == m) ? 32u : 0u;
                mk |= (c6 == m) ? 64u : 0u;
                mk |= (c7 == m) ? 128u : 0u;
                tag = __ffs(mk) - 1;
                path[local][c][h][t - tb] = (unsigned char)tag;
            }
        }
        __syncthreads();

        if (tid == 0 || tid == 64) {
            const int local = tid >> 6;
            int ex = lastsh[local];
            for (int cc = 7; cc >= 0; cc--) {
                sel[local][cc] = (unsigned char)ex;
                ex = path[local][cc][ex][0];
            }
        }
        __syncthreads();

        if (tid < 128) {
            const int local = tid >> 6;
            const int lt    = tid & 63;
            if (lt < 8) {
                const int cc = lt;
                const int tb = cc * 64 + 1;
                const int te = (cc * 64 + 64 < TT) ? cc * 64 + 64 : TT - 1;
                const int stag = sel[local][cc];
                float* pred = out + PRED_OFF + (size_t)(s0 + local) * TT;
                pred[te] = (float)stag;
                const unsigned char* pp = &path[local][cc][stag][0];
                for (int idx = te - tb; idx >= 0; idx--)
                    pred[tb - 1 + idx] = (float)pp[idx];
            }
        }
    } else {
        // =================== matrices + numerator + logZ + loss ===================
        const int s0 = (blockIdx.x - 96) * 2;
        const int kt = s0 >> 6;

        if (tid < 128) {
            // ---- forward chunk basis matrices (linear domain) ----
            const int ib = tid & 7;
            const int c  = (tid >> 3) & 7;
            const int sl = tid >> 6;
            const int s  = s0 + sl;

            float ec[64];
            #pragma unroll
            for (int i = 0; i < 64; i++) ec[i] = __expf(trans[kt * 64 + i]) * 0.125f;

            float P[8];
            #pragma unroll
            for (int jj = 0; jj < 8; jj++) P[jj] = (jj == ib) ? 1.0f : 0.0f;

            const int tb = c * 64 + 1;
            const int te = (c * 64 + 64 < TT) ? c * 64 + 64 : TT - 1;
            const float* eo = g_expo + (size_t)s * (TT * CC);

            float4 pa0 = *reinterpret_cast<const float4*>(eo + tb * 8);
            float4 pb0 = *reinterpret_cast<const float4*>(eo + tb * 8 + 4);
            float4 pa1 = *reinterpret_cast<const float4*>(eo + (tb + 1) * 8);
            float4 pb1 = *reinterpret_cast<const float4*>(eo + (tb + 1) * 8 + 4);

            for (int t = tb; t <= te; t++) {
                float4 ca = pa0, cb = pb0;
                pa0 = pa1; pb0 = pb1;
                int tn = t + 2;
                if (tn <= te) {
                    pa1 = *reinterpret_cast<const float4*>(eo + tn * 8);
                    pb1 = *reinterpret_cast<const float4*>(eo + tn * 8 + 4);
                }
                float np[8];
                #pragma unroll
                for (int jj = 0; jj < 8; jj++) {
                    float sum = P[0] * ec[jj];
                    #pragma unroll
                    for (int i = 1; i < 8; i++) sum = fmaf(P[i], ec[i * 8 + jj], sum);
                    np[jj] = sum;
                }
                P[0] = np[0] * ca.x; P[1] = np[1] * ca.y;
                P[2] = np[2] * ca.z; P[3] = np[3] * ca.w;
                P[4] = np[4] * cb.x; P[5] = np[5] * cb.y;
                P[6] = np[6] * cb.z; P[7] = np[7] * cb.w;
            }
            #pragma unroll
            for (int jj = 0; jj < 8; jj++) Psm[sl][c][ib][jj] = P[jj];
        } else {
            // ---- numerator, MLP-batched gathers (tids 128..143) ----
            const int nid = tid - 128;
            const int sl = nid >> 3, j = nid & 7;
            const int s  = s0 + sl, b = s & 63;
            const float* em = out + LOGITS_OFF + (size_t)s * (TT * CC);
            const int* lab = labels + b * (3 * TT) + kt * TT;
            float num = 0.0f;
            for (int u0 = 0; u0 < 64; u0 += 4) {
                int tg[4], tp[4];
                #pragma unroll
                for (int u = 0; u < 4; u++) {
                    int t = j + 8 * (u0 + u);
                    tg[u] = lab[t];
                    tp[u] = (t > 0) ? lab[t - 1] : 0;
                }
                #pragma unroll
                for (int u = 0; u < 4; u++) {
                    int t = j + 8 * (u0 + u);
                    num += em[t * 8 + tg[u]];
                    num += (t > 0) ? trans[kt * 64 + tp[u] * 8 + tg[u]]
                                   : start_t[kt * 8 + tg[u]];
                    if (t == TT - 1) num += end_t[kt * 8 + tg[u]];
                }
            }
            #pragma unroll
            for (int d = 4; d > 0; d >>= 1) num += __shfl_xor_sync(0xFFFFu, num, d, 8);
            if (j == 0) numsh[sl] = num;
        }
        __syncthreads();

        if (tid < 16) {
            // ---- logZ combine + loss ----
            const int sl = tid >> 3, j = tid & 7;
            const int s  = s0 + sl;
            const float* em = out + LOGITS_OFF + (size_t)s * (TT * CC);
            const float LOG8 = 2.0794415416798357f;

            float a = start_t[kt * 8 + j] + em[j];
            for (int c = 0; c < 8; c++) {
                float n = (c < 7) ? 64.0f : 63.0f;
                float lm[8];
                #pragma unroll
                for (int i = 0; i < 8; i++)
                    lm[i] = __logf(Psm[sl][c][i][j]) + n * LOG8 + __shfl_sync(0xFFFFu, a, i, 8);
                float m = fmaxf(fmaxf(fmaxf(lm[0], lm[1]), fmaxf(lm[2], lm[3])),
                                fmaxf(fmaxf(lm[4], lm[5]), fmaxf(lm[6], lm[7])));
                float ssum = 0.0f;
                #pragma unroll
                for (int i = 0; i < 8; i++) ssum += __expf(lm[i] - m);
                a = m + __logf(ssum);
            }
            float y = a + end_t[kt * 8 + j];
            float mm = y;
            #pragma unroll
            for (int d = 4; d > 0; d >>= 1) mm = fmaxf(mm, __shfl_xor_sync(0xFFFFu, mm, d, 8));
            float q = __expf(y - mm);
            #pragma unroll
            for (int d = 4; d > 0; d >>= 1) q += __shfl_xor_sync(0xFFFFu, q, d, 8);
            float logZ = mm + __logf(q);
            if (j == 0) atomicAdd(&out[0], logZ - numsh[sl]);
        }
    }
}

extern "C" void kernel_launch(void* const* d_in, const int* in_sizes, int n_in,
                              void* d_out, int out_size)
{
    (void)in_sizes; (void)n_in; (void)out_size;
    const float* enc     = (const float*)d_in[0];
    const int*   labels  = (const int*)  d_in[1];
    const float* W       = (const float*)d_in[2];
    const float* bias    = (const float*)d_in[3];
    const float* start_t = (const float*)d_in[4];
    const float* end_t   = (const float*)d_in[5];
    const float* trans   = (const float*)d_in[6];
    float* out = (float*)d_out;

    gemm_kernel<<<256, 128>>>(enc, W, bias, out);
    crf_kernel<<<192, 144>>>(labels, start_t, end_t, trans, out);
}

// round 13
// speedup vs baseline: 1.0607x; 1.0607x over previous
#include <cuda_runtime.h>

#define BB   64
#define TT   512
#define HH   1024
#define CC   8
#define NROW 32768
#define LOGITS_OFF 1
#define PRED_OFF   (1 + 3*BB*TT*CC)
#define FULLM 0xFFFFFFFFu

__device__ float g_expo[3 * NROW * CC];   // exp(logits)

__device__ __forceinline__ void ffma2(unsigned long long& d,
                                      unsigned long long a,
                                      unsigned long long b) {
    asm("fma.rn.f32x2 %0, %1, %2, %0;" : "+l"(d) : "l"(a), "l"(b));
}
__device__ __forceinline__ void cpa16(unsigned sm, const void* g) {
    asm volatile("cp.async.cg.shared.global [%0], [%1], 16;" :: "r"(sm), "l"(g));
}

// ---------------------------------------------------------------------------
// GEMM: M=32768, N=24, K=1024. 256 blocks x 128 threads, 3-stage cp.async.
// Warps 0-1 -> cols 0-11, warps 2-3 -> cols 12-23 (W LDS all-broadcast).
// Thread = rows {rowid, rowid+64} x 12 cols, f32x2 FMA.
// ---------------------------------------------------------------------------
__global__ __launch_bounds__(128) void gemm_kernel(
    const float* __restrict__ enc, const float* __restrict__ W,
    const float* __restrict__ bias, float* __restrict__ out)
{
    __shared__ float As[3][128 * 20];
    __shared__ float Ws[3][24 * 20];

    const int tid   = threadIdx.x;
    const int wid   = tid >> 5;
    const int lane  = tid & 31;
    const int rb    = blockIdx.x * 128;
    const int c0    = (wid >> 1) * 12;
    const int rowid = (wid & 1) * 32 + lane;
    if (blockIdx.x == 0 && tid == 0) out[0] = 0.0f;

    unsigned long long acc[2][12];
    #pragma unroll
    for (int h = 0; h < 2; h++)
        #pragma unroll
        for (int m = 0; m < 12; m++) acc[h][m] = 0ull;

    unsigned asB[3] = { (unsigned)__cvta_generic_to_shared(&As[0][0]),
                        (unsigned)__cvta_generic_to_shared(&As[1][0]),
                        (unsigned)__cvta_generic_to_shared(&As[2][0]) };
    unsigned wsB[3] = { (unsigned)__cvta_generic_to_shared(&Ws[0][0]),
                        (unsigned)__cvta_generic_to_shared(&Ws[1][0]),
                        (unsigned)__cvta_generic_to_shared(&Ws[2][0]) };

    auto load_tiles = [&](int kb, int bf) {
        #pragma unroll
        for (int i = 0; i < 4; i++) {
            int idx = tid + i * 128;
            int row = idx >> 2, q = idx & 3;
            cpa16(asB[bf] + (row * 20 + q * 4) * 4,
                  enc + (size_t)(rb + row) * HH + kb + q * 4);
        }
        if (tid < 96) {
            int c = tid >> 2, q = tid & 3;
            cpa16(wsB[bf] + (c * 20 + q * 4) * 4, W + (size_t)c * HH + kb + q * 4);
        }
        asm volatile("cp.async.commit_group;");
    };

    load_tiles(0, 0);
    load_tiles(16, 1);
    int buf = 0;
    for (int kb = 0; kb < HH; kb += 16) {
        if (kb + 32 < HH) {
            load_tiles(kb + 32, (buf + 2) % 3);
            asm volatile("cp.async.wait_group 2;");
        } else if (kb + 16 < HH) {
            asm volatile("cp.async.wait_group 1;");
        } else {
            asm volatile("cp.async.wait_group 0;");
        }
        __syncthreads();
        #pragma unroll
        for (int k4 = 0; k4 < 16; k4 += 4) {
            ulonglong2 a0 = *reinterpret_cast<const ulonglong2*>(&As[buf][rowid * 20 + k4]);
            ulonglong2 a1 = *reinterpret_cast<const ulonglong2*>(&As[buf][(rowid + 64) * 20 + k4]);
            #pragma unroll
            for (int m = 0; m < 12; m++) {
                ulonglong2 wv = *reinterpret_cast<const ulonglong2*>(&Ws[buf][(c0 + m) * 20 + k4]);
                ffma2(acc[0][m], a0.x, wv.x);
                ffma2(acc[0][m], a0.y, wv.y);
                ffma2(acc[1][m], a1.x, wv.x);
                ffma2(acc[1][m], a1.y, wv.y);
            }
        }
        __syncthreads();
        buf = (buf + 1) % 3;
    }

    #pragma unroll
    for (int h = 0; h < 2; h++) {
        const int r = rb + rowid + 64 * h;
        #pragma unroll
        for (int m = 0; m < 12; m++) {
            int col = c0 + m;
            int kt = col >> 3, cc = col & 7;
            float2 f = *reinterpret_cast<float2*>(&acc[h][m]);
            float val = f.x + f.y + bias[col];
            size_t base = ((size_t)kt * NROW + r) * 8 + cc;
            out[LOGITS_OFF + base] = val;
            g_expo[base] = __expf(val);
        }
    }
}

// ---------------------------------------------------------------------------
// crf: 192 blocks x 160 threads, 2 sequences per block.
// Blocks 0..95   : Viterbi chain (warp0, ALL 32 lanes active: lanes 16-31
//                  duplicate lanes 0-15 so full-mask shfl => no WARPSYNC)
//                  then decode from smem v.
// Blocks 96..191 : forward chunk matrices + numerator + logZ + loss.
// ---------------------------------------------------------------------------
__global__ __launch_bounds__(160) void crf_kernel(
    const int* __restrict__ labels, const float* __restrict__ start_t,
    const float* __restrict__ end_t, const float* __restrict__ trans,
    float* __restrict__ out)
{
    __shared__ float         vsm[2][TT][8];        // 32KB
    __shared__ unsigned char path[2][8][8][64];    // 8KB
    __shared__ unsigned char sel[2][8];
    __shared__ float         strT[64];
    __shared__ int           lastsh[2];
    __shared__ float         Psm[2][8][8][8];
    __shared__ float         numsh[2];

    const int tid  = threadIdx.x;
    const int lane = tid & 31;

    if (blockIdx.x < 96) {
        // =================== chain + decode block ===================
        const int s0 = blockIdx.x * 2;
        const int kt = s0 >> 6;

        if (tid < 64) strT[tid] = trans[kt * 64 + (tid & 7) * 8 + (tid >> 3)];

        if (tid < 32) {
            // lanes 0-7: seq0, 8-15: seq1, 16-23: seq0 dup, 24-31: seq1 dup
            const int sl = (lane >> 3) & 1, j = lane & 7;
            const int s  = s0 + sl;
            const float* em = out + LOGITS_OFF + (size_t)s * (TT * CC);

            float tr[8];
            #pragma unroll
            for (int i = 0; i < 8; i++) tr[i] = trans[kt * 64 + i * 8 + j];

            float v = start_t[kt * 8 + j] + em[j];
            if (lane < 16) vsm[sl][0][j] = v;

            float eb[8];
            #pragma unroll
            for (int u = 0; u < 8; u++) eb[u] = em[(1 + u) * 8 + j];

            for (int tw = 1; tw < TT; tw += 8) {
                float nb[8];
                #pragma unroll
                for (int u = 0; u < 8; u++) {
                    int tn = tw + 8 + u;
                    nb[u] = (tn < TT) ? em[tn * 8 + j] : 0.0f;
                }
                #pragma unroll
                for (int u = 0; u < 8; u++) {
                    int t = tw + u;
                    if (t < TT) {
                        float c0 = __shfl_sync(FULLM, v, 0, 8) + tr[0];
                        float c1 = __shfl_sync(FULLM, v, 1, 8) + tr[1];
                        float c2 = __shfl_sync(FULLM, v, 2, 8) + tr[2];
                        float c3 = __shfl_sync(FULLM, v, 3, 8) + tr[3];
                        float c4 = __shfl_sync(FULLM, v, 4, 8) + tr[4];
                        float c5 = __shfl_sync(FULLM, v, 5, 8) + tr[5];
                        float c6 = __shfl_sync(FULLM, v, 6, 8) + tr[6];
                        float c7 = __shfl_sync(FULLM, v, 7, 8) + tr[7];
                        float m = fmaxf(fmaxf(fmaxf(c0, c1), fmaxf(c2, c3)),
                                        fmaxf(fmaxf(c4, c5), fmaxf(c6, c7)));
                        v = m + eb[u];
                        if (lane < 16) vsm[sl][t][j] = v;
                    }
                }
                #pragma unroll
                for (int u = 0; u < 8; u++) eb[u] = nb[u];
            }

            float y = v + end_t[kt * 8 + j];
            float g[8];
            #pragma unroll
            for (int i = 0; i < 8; i++) g[i] = __shfl_sync(FULLM, y, i, 8);
            float bv = g[0]; int last = 0;
            #pragma unroll
            for (int i = 1; i < 8; i++) { if (g[i] > bv) { bv = g[i]; last = i; } }
            if (lane < 16 && j == 0) lastsh[sl] = last;
        }
        __syncthreads();

        if (tid >= 32) {
            // ---- decode: per (seq, chunk, hypothesis) backtrace ----
            const int did   = tid - 32;
            const int local = did >> 6;
            const int lt    = did & 63;
            const int c  = lt >> 3, h = lt & 7;
            const int tb = c * 64 + 1;
            const int te = (c * 64 + 64 < TT) ? c * 64 + 64 : TT - 1;
            int tag = h;
            for (int t = te; t >= tb; t--) {
                float4 va = *reinterpret_cast<const float4*>(&vsm[local][t - 1][0]);
                float4 vb = *reinterpret_cast<const float4*>(&vsm[local][t - 1][4]);
                const float* tc = &strT[tag * 8];
                float c0 = va.x + tc[0], c1 = va.y + tc[1];
                float c2 = va.z + tc[2], c3 = va.w + tc[3];
                float c4 = vb.x + tc[4], c5 = vb.y + tc[5];
                float c6 = vb.z + tc[6], c7 = vb.w + tc[7];
                float m = fmaxf(fmaxf(fmaxf(c0, c1), fmaxf(c2, c3)),
                                fmaxf(fmaxf(c4, c5), fmaxf(c6, c7)));
                unsigned mk = (c0 == m) ? 1u : 0u;
                mk |= (c1 == m) ? 2u : 0u;
                mk |= (c2 == m) ? 4u : 0u;
                mk |= (c3 == m) ? 8u : 0u;
                mk |= (c4 == m) ? 16u : 0u;
                mk |= (c5 == m) ? 32u : 0u;
                mk |= (c6 == m) ? 64u : 0u;
                mk |= (c7 == m) ? 128u : 0u;
                tag = __ffs(mk) - 1;
                path[local][c][h][t - tb] = (unsigned char)tag;
            }
        }
        __syncthreads();

        if (tid == 32 || tid == 96) {
            const int local = (tid - 32) >> 6;
            int ex = lastsh[local];
            for (int cc = 7; cc >= 0; cc--) {
                sel[local][cc] = (unsigned char)ex;
                ex = path[local][cc][ex][0];
            }
        }
        __syncthreads();

        if (tid >= 32) {
            const int did   = tid - 32;
            const int local = did >> 6;
            const int lt    = did & 63;
            if (lt < 8) {
                const int cc = lt;
                const int tb = cc * 64 + 1;
                const int te = (cc * 64 + 64 < TT) ? cc * 64 + 64 : TT - 1;
                const int stag = sel[local][cc];
                float* pred = out + PRED_OFF + (size_t)(s0 + local) * TT;
                pred[te] = (float)stag;
                const unsigned char* pp = &path[local][cc][stag][0];
                for (int idx = te - tb; idx >= 0; idx--)
                    pred[tb - 1 + idx] = (float)pp[idx];
            }
        }
    } else {
        // =================== matrices + numerator + logZ + loss ===================
        const int s0 = (blockIdx.x - 96) * 2;
        const int kt = s0 >> 6;

        if (tid < 128) {
            const int ib = tid & 7;
            const int c  = (tid >> 3) & 7;
            const int sl = tid >> 6;
            const int s  = s0 + sl;

            float ec[64];
            #pragma unroll
            for (int i = 0; i < 64; i++) ec[i] = __expf(trans[kt * 64 + i]) * 0.125f;

            float P[8];
            #pragma unroll
            for (int jj = 0; jj < 8; jj++) P[jj] = (jj == ib) ? 1.0f : 0.0f;

            const int tb = c * 64 + 1;
            const int te = (c * 64 + 64 < TT) ? c * 64 + 64 : TT - 1;
            const float* eo = g_expo + (size_t)s * (TT * CC);

            float4 pa0 = *reinterpret_cast<const float4*>(eo + tb * 8);
            float4 pb0 = *reinterpret_cast<const float4*>(eo + tb * 8 + 4);
            float4 pa1 = *reinterpret_cast<const float4*>(eo + (tb + 1) * 8);
            float4 pb1 = *reinterpret_cast<const float4*>(eo + (tb + 1) * 8 + 4);

            for (int t = tb; t <= te; t++) {
                float4 ca = pa0, cb = pb0;
                pa0 = pa1; pb0 = pb1;
                int tn = t + 2;
                if (tn <= te) {
                    pa1 = *reinterpret_cast<const float4*>(eo + tn * 8);
                    pb1 = *reinterpret_cast<const float4*>(eo + tn * 8 + 4);
                }
                float np[8];
                #pragma unroll
                for (int jj = 0; jj < 8; jj++) {
                    float sum = P[0] * ec[jj];
                    #pragma unroll
                    for (int i = 1; i < 8; i++) sum = fmaf(P[i], ec[i * 8 + jj], sum);
                    np[jj] = sum;
                }
                P[0] = np[0] * ca.x; P[1] = np[1] * ca.y;
                P[2] = np[2] * ca.z; P[3] = np[3] * ca.w;
                P[4] = np[4] * cb.x; P[5] = np[5] * cb.y;
                P[6] = np[6] * cb.z; P[7] = np[7] * cb.w;
            }
            #pragma unroll
            for (int jj = 0; jj < 8; jj++) Psm[sl][c][ib][jj] = P[jj];
        } else {
            // ---- numerator (tids 128..143 = lanes 0..15 of warp 4) ----
            const int nid = tid - 128;
            if (nid < 16) {
                const int sl = nid >> 3, j = nid & 7;
                const int s  = s0 + sl, b = s & 63;
                const float* em = out + LOGITS_OFF + (size_t)s * (TT * CC);
                const int* lab = labels + b * (3 * TT) + kt * TT;
                float num = 0.0f;
                for (int u0 = 0; u0 < 64; u0 += 4) {
                    int tg[4], tp[4];
                    #pragma unroll
                    for (int u = 0; u < 4; u++) {
                        int t = j + 8 * (u0 + u);
                        tg[u] = lab[t];
                        tp[u] = (t > 0) ? lab[t - 1] : 0;
                    }
                    #pragma unroll
                    for (int u = 0; u < 4; u++) {
                        int t = j + 8 * (u0 + u);
                        num += em[t * 8 + tg[u]];
                        num += (t > 0) ? trans[kt * 64 + tp[u] * 8 + tg[u]]
                                       : start_t[kt * 8 + tg[u]];
                        if (t == TT - 1) num += end_t[kt * 8 + tg[u]];
                    }
                }
                #pragma unroll
                for (int d = 4; d > 0; d >>= 1) num += __shfl_xor_sync(0xFFFFu, num, d, 8);
                if (j == 0) numsh[sl] = num;
            }
        }
        __syncthreads();

        if (tid < 16) {
            const int sl = tid >> 3, j = tid & 7;
            const int s  = s0 + sl;
            const float* em = out + LOGITS_OFF + (size_t)s * (TT * CC);
            const float LOG8 = 2.0794415416798357f;

            float a = start_t[kt * 8 + j] + em[j];
            for (int c = 0; c < 8; c++) {
                float n = (c < 7) ? 64.0f : 63.0f;
                float lm[8];
                #pragma unroll
                for (int i = 0; i < 8; i++)
                    lm[i] = __logf(Psm[sl][c][i][j]) + n * LOG8 + __shfl_sync(0xFFFFu, a, i, 8);
                float m = fmaxf(fmaxf(fmaxf(lm[0], lm[1]), fmaxf(lm[2], lm[3])),
                                fmaxf(fmaxf(lm[4], lm[5]), fmaxf(lm[6], lm[7])));
                float ssum = 0.0f;
                #pragma unroll
                for (int i = 0; i < 8; i++) ssum += __expf(lm[i] - m);
                a = m + __logf(ssum);
            }
            float y = a + end_t[kt * 8 + j];
            float mm = y;
            #pragma unroll
            for (int d = 4; d > 0; d >>= 1) mm = fmaxf(mm, __shfl_xor_sync(0xFFFFu, mm, d, 8));
            float q = __expf(y - mm);
            #pragma unroll
            for (int d = 4; d > 0; d >>= 1) q += __shfl_xor_sync(0xFFFFu, q, d, 8);
            float logZ = mm + __logf(q);
            if (j == 0) atomicAdd(&out[0], logZ - numsh[sl]);
        }
    }
}

extern "C" void kernel_launch(void* const* d_in, const int* in_sizes, int n_in,
                              void* d_out, int out_size)
{
    (void)in_sizes; (void)n_in; (void)out_size;
    const float* enc     = (const float*)d_in[0];
    const int*   labels  = (const int*)  d_in[1];
    const float* W       = (const float*)d_in[2];
    const float* bias    = (const float*)d_in[3];
    const float* start_t = (const float*)d_in[4];
    const float* end_t   = (const float*)d_in[5];
    const float* trans   = (const float*)d_in[6];
    float* out = (float*)d_out;

    gemm_kernel<<<256, 128>>>(enc, W, bias, out);
    crf_kernel<<<192, 160>>>(labels, start_t, end_t, trans, out);
}

// round 14
// speedup vs baseline: 1.1407x; 1.0754x over previous
#include <cuda_runtime.h>

#define BB   64
#define TT   512
#define HH   1024
#define CC   8
#define NROW 32768
#define NLOG (3 * NROW * CC)
#define LOGITS_OFF 1
#define PRED_OFF   (1 + 3*BB*TT*CC)
#define FULLM 0xFFFFFFFFu

__device__ float g_expo[NLOG];    // exp(logits)
__device__ float g_part0[NLOG];   // split-K partial (k 0..511) + bias
__device__ float g_part1[NLOG];   // split-K partial (k 512..1023)

__device__ __forceinline__ void ffma2(unsigned long long& d,
                                      unsigned long long a,
                                      unsigned long long b) {
    asm("fma.rn.f32x2 %0, %1, %2, %0;" : "+l"(d) : "l"(a), "l"(b));
}
__device__ __forceinline__ void cpa16(unsigned sm, const void* g) {
    asm volatile("cp.async.cg.shared.global [%0], [%1], 16;" :: "r"(sm), "l"(g));
}

// ---------------------------------------------------------------------------
// GEMM split-K2: 512 blocks x 128 threads; blockIdx>>8 selects K-half.
// Block tile 128 rows x 24 cols x K=512. Warps 0-1 cols 0-11, 2-3 cols 12-23
// (W LDS all-broadcast). Thread = rows {rowid, rowid+64} x 12 cols, f32x2.
// ---------------------------------------------------------------------------
__global__ __launch_bounds__(128) void gemm_kernel(
    const float* __restrict__ enc, const float* __restrict__ W,
    const float* __restrict__ bias, float* __restrict__ out)
{
    __shared__ float As[3][128 * 20];
    __shared__ float Ws[3][24 * 20];

    const int tid   = threadIdx.x;
    const int wid   = tid >> 5;
    const int lane  = tid & 31;
    const int kh    = blockIdx.x >> 8;          // K half
    const int kb0   = kh * 512;
    const int rb    = (blockIdx.x & 255) * 128;
    const int c0    = (wid >> 1) * 12;
    const int rowid = (wid & 1) * 32 + lane;
    if (blockIdx.x == 0 && tid == 0) out[0] = 0.0f;

    unsigned long long acc[2][12];
    #pragma unroll
    for (int h = 0; h < 2; h++)
        #pragma unroll
        for (int m = 0; m < 12; m++) acc[h][m] = 0ull;

    unsigned asB[3] = { (unsigned)__cvta_generic_to_shared(&As[0][0]),
                        (unsigned)__cvta_generic_to_shared(&As[1][0]),
                        (unsigned)__cvta_generic_to_shared(&As[2][0]) };
    unsigned wsB[3] = { (unsigned)__cvta_generic_to_shared(&Ws[0][0]),
                        (unsigned)__cvta_generic_to_shared(&Ws[1][0]),
                        (unsigned)__cvta_generic_to_shared(&Ws[2][0]) };

    auto load_tiles = [&](int kb, int bf) {
        #pragma unroll
        for (int i = 0; i < 4; i++) {
            int idx = tid + i * 128;
            int row = idx >> 2, q = idx & 3;
            cpa16(asB[bf] + (row * 20 + q * 4) * 4,
                  enc + (size_t)(rb + row) * HH + kb + q * 4);
        }
        if (tid < 96) {
            int c = tid >> 2, q = tid & 3;
            cpa16(wsB[bf] + (c * 20 + q * 4) * 4, W + (size_t)c * HH + kb + q * 4);
        }
        asm volatile("cp.async.commit_group;");
    };

    load_tiles(kb0, 0);
    load_tiles(kb0 + 16, 1);
    int buf = 0;
    for (int ki = 0; ki < 512; ki += 16) {
        if (ki + 32 < 512) {
            load_tiles(kb0 + ki + 32, (buf + 2) % 3);
            asm volatile("cp.async.wait_group 2;");
        } else if (ki + 16 < 512) {
            asm volatile("cp.async.wait_group 1;");
        } else {
            asm volatile("cp.async.wait_group 0;");
        }
        __syncthreads();
        #pragma unroll
        for (int k4 = 0; k4 < 16; k4 += 4) {
            ulonglong2 a0 = *reinterpret_cast<const ulonglong2*>(&As[buf][rowid * 20 + k4]);
            ulonglong2 a1 = *reinterpret_cast<const ulonglong2*>(&As[buf][(rowid + 64) * 20 + k4]);
            #pragma unroll
            for (int m = 0; m < 12; m++) {
                ulonglong2 wv = *reinterpret_cast<const ulonglong2*>(&Ws[buf][(c0 + m) * 20 + k4]);
                ffma2(acc[0][m], a0.x, wv.x);
                ffma2(acc[0][m], a0.y, wv.y);
                ffma2(acc[1][m], a1.x, wv.x);
                ffma2(acc[1][m], a1.y, wv.y);
            }
        }
        __syncthreads();
        buf = (buf + 1) % 3;
    }

    float* dst = kh ? g_part1 : g_part0;
    #pragma unroll
    for (int h = 0; h < 2; h++) {
        const int r = rb + rowid + 64 * h;
        #pragma unroll
        for (int m = 0; m < 12; m++) {
            int col = c0 + m;
            int kt = col >> 3, cc = col & 7;
            float2 f = *reinterpret_cast<float2*>(&acc[h][m]);
            float val = f.x + f.y + (kh ? 0.0f : bias[col]);
            dst[((size_t)kt * NROW + r) * 8 + cc] = val;
        }
    }
}

// combine: logits = p0 + p1; write to out and exp to g_expo
__global__ __launch_bounds__(256) void combine_kernel(float* __restrict__ out)
{
    const int i4 = (blockIdx.x * 256 + threadIdx.x) * 4;
    float4 p0 = *reinterpret_cast<const float4*>(&g_part0[i4]);
    float4 p1 = *reinterpret_cast<const float4*>(&g_part1[i4]);
    float v0 = p0.x + p1.x, v1 = p0.y + p1.y, v2 = p0.z + p1.z, v3 = p0.w + p1.w;
    out[LOGITS_OFF + i4 + 0] = v0;
    out[LOGITS_OFF + i4 + 1] = v1;
    out[LOGITS_OFF + i4 + 2] = v2;
    out[LOGITS_OFF + i4 + 3] = v3;
    float4 e = { __expf(v0), __expf(v1), __expf(v2), __expf(v3) };
    *reinterpret_cast<float4*>(&g_expo[i4]) = e;
}

// ---------------------------------------------------------------------------
// crf: 192 blocks x 160 threads, 2 sequences per block.
// Blocks 0..95: Viterbi chain (warp0: lanes 0-15 = partial max over prev
//   states 0-3, lanes 16-31 = over 4-7, combined by shfl.xor(16) — exact),
//   then decode. Blocks 96..191: forward matrices + numerator + logZ + loss.
// ---------------------------------------------------------------------------
__global__ __launch_bounds__(160) void crf_kernel(
    const int* __restrict__ labels, const float* __restrict__ start_t,
    const float* __restrict__ end_t, const float* __restrict__ trans,
    float* __restrict__ out)
{
    __shared__ float         vsm[2][TT][8];        // 32KB
    __shared__ unsigned char path[2][8][8][64];    // 8KB
    __shared__ unsigned char sel[2][8];
    __shared__ float         strT[64];
    __shared__ int           lastsh[2];
    __shared__ float         Psm[2][8][8][8];
    __shared__ float         numsh[2];

    const int tid  = threadIdx.x;
    const int lane = tid & 31;

    if (blockIdx.x < 96) {
        // =================== chain + decode block ===================
        const int s0 = blockIdx.x * 2;
        const int kt = s0 >> 6;

        if (tid < 64) strT[tid] = trans[kt * 64 + (tid & 7) * 8 + (tid >> 3)];

        if (tid < 32) {
            // lanes 0-7: seq0 / rows 0-3, 8-15: seq1 / rows 0-3,
            // 16-23: seq0 / rows 4-7, 24-31: seq1 / rows 4-7
            const int sl    = (lane >> 3) & 1;
            const int j     = lane & 7;
            const int rbase = (lane >> 4) * 4;
            const int s     = s0 + sl;
            const float* em = out + LOGITS_OFF + (size_t)s * (TT * CC);

            float tr[4];
            #pragma unroll
            for (int r = 0; r < 4; r++) tr[r] = trans[kt * 64 + (rbase + r) * 8 + j];

            float v = start_t[kt * 8 + j] + em[j];
            if (lane < 16) vsm[sl][0][j] = v;

            float eb[8];
            #pragma unroll
            for (int u = 0; u < 8; u++) eb[u] = em[(1 + u) * 8 + j];

            for (int tw = 1; tw < TT - 14; tw += 8) {   // full windows, t=1..504
                float nb[8];
                #pragma unroll
                for (int u = 0; u < 8; u++) nb[u] = em[(tw + 8 + u) * 8 + j];
                #pragma unroll
                for (int u = 0; u < 8; u++) {
                    const int t = tw + u;
                    float c0 = __shfl_sync(FULLM, v, rbase + 0, 8) + tr[0];
                    float c1 = __shfl_sync(FULLM, v, rbase + 1, 8) + tr[1];
                    float c2 = __shfl_sync(FULLM, v, rbase + 2, 8) + tr[2];
                    float c3 = __shfl_sync(FULLM, v, rbase + 3, 8) + tr[3];
                    float pm = fmaxf(fmaxf(c0, c1), fmaxf(c2, c3));
                    float om = __shfl_xor_sync(FULLM, pm, 16, 32);
                    float m  = fmaxf(pm, om);
                    v = m + eb[u];
                    if (lane < 16) vsm[sl][t][j] = v;
                }
                #pragma unroll
                for (int u = 0; u < 8; u++) eb[u] = nb[u];
            }
            #pragma unroll
            for (int u = 0; u < 7; u++) {               // peel t=505..511
                const int t = (TT - 7) + u;
                float c0 = __shfl_sync(FULLM, v, rbase + 0, 8) + tr[0];
                float c1 = __shfl_sync(FULLM, v, rbase + 1, 8) + tr[1];
                float c2 = __shfl_sync(FULLM, v, rbase + 2, 8) + tr[2];
                float c3 = __shfl_sync(FULLM, v, rbase + 3, 8) + tr[3];
                float pm = fmaxf(fmaxf(c0, c1), fmaxf(c2, c3));
                float om = __shfl_xor_sync(FULLM, pm, 16, 32);
                float m  = fmaxf(pm, om);
                v = m + eb[u];
                if (lane < 16) vsm[sl][t][j] = v;
            }

            float y = v + end_t[kt * 8 + j];
            float g[8];
            #pragma unroll
            for (int i = 0; i < 8; i++) g[i] = __shfl_sync(FULLM, y, i, 8);
            float bv = g[0]; int last = 0;
            #pragma unroll
            for (int i = 1; i < 8; i++) { if (g[i] > bv) { bv = g[i]; last = i; } }
            if (lane < 16 && j == 0) lastsh[sl] = last;
        }
        __syncthreads();

        if (tid >= 32) {
            // ---- decode: per (seq, chunk, hypothesis) backtrace ----
            const int did   = tid - 32;
            const int local = did >> 6;
            const int lt    = did & 63;
            const int c  = lt >> 3, h = lt & 7;
            const int tb = c * 64 + 1;
            const int te = (c * 64 + 64 < TT) ? c * 64 + 64 : TT - 1;
            int tag = h;
            for (int t = te; t >= tb; t--) {
                float4 va = *reinterpret_cast<const float4*>(&vsm[local][t - 1][0]);
                float4 vb = *reinterpret_cast<const float4*>(&vsm[local][t - 1][4]);
                const float* tc = &strT[tag * 8];
                float c0 = va.x + tc[0], c1 = va.y + tc[1];
                float c2 = va.z + tc[2], c3 = va.w + tc[3];
                float c4 = vb.x + tc[4], c5 = vb.y + tc[5];
                float c6 = vb.z + tc[6], c7 = vb.w + tc[7];
                float m = fmaxf(fmaxf(fmaxf(c0, c1), fmaxf(c2, c3)),
                                fmaxf(fmaxf(c4, c5), fmaxf(c6, c7)));
                unsigned mk = (c0 == m) ? 1u : 0u;
                mk |= (c1 == m) ? 2u : 0u;
                mk |= (c2 == m) ? 4u : 0u;
                mk |= (c3 == m) ? 8u : 0u;
                mk |= (c4 == m) ? 16u : 0u;
                mk |= (c5 == m) ? 32u : 0u;
                mk |= (c6 == m) ? 64u : 0u;
                mk |= (c7 == m) ? 128u : 0u;
                tag = __ffs(mk) - 1;
                path[local][c][h][t - tb] = (unsigned char)tag;
            }
        }
        __syncthreads();

        if (tid == 32 || tid == 96) {
            const int local = (tid - 32) >> 6;
            int ex = lastsh[local];
            for (int cc = 7; cc >= 0; cc--) {
                sel[local][cc] = (unsigned char)ex;
                ex = path[local][cc][ex][0];
            }
        }
        __syncthreads();

        if (tid >= 32) {
            const int did   = tid - 32;
            const int local = did >> 6;
            const int lt    = did & 63;
            if (lt < 8) {
                const int cc = lt;
                const int tb = cc * 64 + 1;
                const int te = (cc * 64 + 64 < TT) ? cc * 64 + 64 : TT - 1;
                const int stag = sel[local][cc];
                float* pred = out + PRED_OFF + (size_t)(s0 + local) * TT;
                pred[te] = (float)stag;
                const unsigned char* pp = &path[local][cc][stag][0];
                for (int idx = te - tb; idx >= 0; idx--)
                    pred[tb - 1 + idx] = (float)pp[idx];
            }
        }
    } else {
        // =================== matrices + numerator + logZ + loss ===================
        const int s0 = (blockIdx.x - 96) * 2;
        const int kt = s0 >> 6;

        if (tid < 128) {
            const int ib = tid & 7;
            const int c  = (tid >> 3) & 7;
            const int sl = tid >> 6;
            const int s  = s0 + sl;

            float ec[64];
            #pragma unroll
            for (int i = 0; i < 64; i++) ec[i] = __expf(trans[kt * 64 + i]) * 0.125f;

            float P[8];
            #pragma unroll
            for (int jj = 0; jj < 8; jj++) P[jj] = (jj == ib) ? 1.0f : 0.0f;

            const int tb = c * 64 + 1;
            const int te = (c * 64 + 64 < TT) ? c * 64 + 64 : TT - 1;
            const float* eo = g_expo + (size_t)s * (TT * CC);

            float4 pa0 = *reinterpret_cast<const float4*>(eo + tb * 8);
            float4 pb0 = *reinterpret_cast<const float4*>(eo + tb * 8 + 4);
            float4 pa1 = *reinterpret_cast<const float4*>(eo + (tb + 1) * 8);
            float4 pb1 = *reinterpret_cast<const float4*>(eo + (tb + 1) * 8 + 4);

            for (int t = tb; t <= te; t++) {
                float4 ca = pa0, cb = pb0;
                pa0 = pa1; pb0 = pb1;
                int tn = t + 2;
                if (tn <= te) {
                    pa1 = *reinterpret_cast<const float4*>(eo + tn * 8);
                    pb1 = *reinterpret_cast<const float4*>(eo + tn * 8 + 4);
                }
                float np[8];
                #pragma unroll
                for (int jj = 0; jj < 8; jj++) {
                    float sum = P[0] * ec[jj];
                    #pragma unroll
                    for (int i = 1; i < 8; i++) sum = fmaf(P[i], ec[i * 8 + jj], sum);
                    np[jj] = sum;
                }
                P[0] = np[0] * ca.x; P[1] = np[1] * ca.y;
                P[2] = np[2] * ca.z; P[3] = np[3] * ca.w;
                P[4] = np[4] * cb.x; P[5] = np[5] * cb.y;
                P[6] = np[6] * cb.z; P[7] = np[7] * cb.w;
            }
            #pragma unroll
            for (int jj = 0; jj < 8; jj++) Psm[sl][c][ib][jj] = P[jj];
        } else {
            // ---- numerator (tids 128..143 = lanes 0..15 of warp 4) ----
            const int nid = tid - 128;
            if (nid < 16) {
                const int sl = nid >> 3, j = nid & 7;
                const int s  = s0 + sl, b = s & 63;
                const float* em = out + LOGITS_OFF + (size_t)s * (TT * CC);
                const int* lab = labels + b * (3 * TT) + kt * TT;
                float num = 0.0f;
                for (int u0 = 0; u0 < 64; u0 += 4) {
                    int tg[4], tp[4];
                    #pragma unroll
                    for (int u = 0; u < 4; u++) {
                        int t = j + 8 * (u0 + u);
                        tg[u] = lab[t];
                        tp[u] = (t > 0) ? lab[t - 1] : 0;
                    }
                    #pragma unroll
                    for (int u = 0; u < 4; u++) {
                        int t = j + 8 * (u0 + u);
                        num += em[t * 8 + tg[u]];
                        num += (t > 0) ? trans[kt * 64 + tp[u] * 8 + tg[u]]
                                       : start_t[kt * 8 + tg[u]];
                        if (t == TT - 1) num += end_t[kt * 8 + tg[u]];
                    }
                }
                #pragma unroll
                for (int d = 4; d > 0; d >>= 1) num += __shfl_xor_sync(0xFFFFu, num, d, 8);
                if (j == 0) numsh[sl] = num;
            }
        }
        __syncthreads();

        if (tid < 16) {
            const int sl = tid >> 3, j = tid & 7;
            const int s  = s0 + sl;
            const float* em = out + LOGITS_OFF + (size_t)s * (TT * CC);
            const float LOG8 = 2.0794415416798357f;

            float a = start_t[kt * 8 + j] + em[j];
            for (int c = 0; c < 8; c++) {
                float n = (c < 7) ? 64.0f : 63.0f;
                float lm[8];
                #pragma unroll
                for (int i = 0; i < 8; i++)
                    lm[i] = __logf(Psm[sl][c][i][j]) + n * LOG8 + __shfl_sync(0xFFFFu, a, i, 8);
                float m = fmaxf(fmaxf(fmaxf(lm[0], lm[1]), fmaxf(lm[2], lm[3])),
                                fmaxf(fmaxf(lm[4], lm[5]), fmaxf(lm[6], lm[7])));
                float ssum = 0.0f;
                #pragma unroll
                for (int i = 0; i < 8; i++) ssum += __expf(lm[i] - m);
                a = m + __logf(ssum);
            }
            float y = a + end_t[kt * 8 + j];
            float mm = y;
            #pragma unroll
            for (int d = 4; d > 0; d >>= 1) mm = fmaxf(mm, __shfl_xor_sync(0xFFFFu, mm, d, 8));
            float q = __expf(y - mm);
            #pragma unroll
            for (int d = 4; d > 0; d >>= 1) q += __shfl_xor_sync(0xFFFFu, q, d, 8);
            float logZ = mm + __logf(q);
            if (j == 0) atomicAdd(&out[0], logZ - numsh[sl]);
        }
    }
}

extern "C" void kernel_launch(void* const* d_in, const int* in_sizes, int n_in,
                              void* d_out, int out_size)
{
    (void)in_sizes; (void)n_in; (void)out_size;
    const float* enc     = (const float*)d_in[0];
    const int*   labels  = (const int*)  d_in[1];
    const float* W       = (const float*)d_in[2];
    const float* bias    = (const float*)d_in[3];
    const float* start_t = (const float*)d_in[4];
    const float* end_t   = (const float*)d_in[5];
    const float* trans   = (const float*)d_in[6];
    float* out = (float*)d_out;

    gemm_kernel   <<<512, 128>>>(enc, W, bias, out);
    combine_kernel<<<NLOG / 1024, 256>>>(out);
    crf_kernel    <<<192, 160>>>(labels, start_t, end_t, trans, out);
}

// round 15
// speedup vs baseline: 1.1689x; 1.0247x over previous
#include <cuda_runtime.h>

#define BB   64
#define TT   512
#define HH   1024
#define CC   8
#define NROW 32768
#define NLOG (3 * NROW * CC)
#define LOGITS_OFF 1
#define PRED_OFF   (1 + 3*BB*TT*CC)
#define FULLM 0xFFFFFFFFu

__device__ float g_expo[NLOG];    // exp(logits)
__device__ float g_part0[NLOG];   // split-K partial (k 0..511) + bias
__device__ float g_part1[NLOG];   // split-K partial (k 512..1023)

__device__ __forceinline__ void ffma2(unsigned long long& d,
                                      unsigned long long a,
                                      unsigned long long b) {
    asm("fma.rn.f32x2 %0, %1, %2, %0;" : "+l"(d) : "l"(a), "l"(b));
}
__device__ __forceinline__ void cpa16(unsigned sm, const void* g) {
    asm volatile("cp.async.cg.shared.global [%0], [%1], 16;" :: "r"(sm), "l"(g));
}

// ---------------------------------------------------------------------------
// GEMM split-K2: 512 blocks x 128 threads. kh = blockIdx&1 selects K-half.
// Block tile 128 rows x 24 cols x K=512. Warp w: colgroup w&1 (12 cols,
// W LDS all-broadcast), k-sub (w>>1) of each k16 tile. Thread = 4 rows
// (lane+32i) x 12 cols = 48 f32x2 accumulators. Warp-pair partials combined
// through smem at the end.
// ---------------------------------------------------------------------------
__global__ __launch_bounds__(128) void gemm_kernel(
    const float* __restrict__ enc, const float* __restrict__ W,
    const float* __restrict__ bias, float* __restrict__ out)
{
    __shared__ float As[3][128 * 20];
    __shared__ float Ws[3][24 * 20];
    __shared__ float red[2][32][48];

    const int tid  = threadIdx.x;
    const int wid  = tid >> 5;
    const int lane = tid & 31;
    const int kh   = blockIdx.x & 1;
    const int rb   = (blockIdx.x >> 1) * 128;
    const int kb0  = kh * 512;
    const int cg   = wid & 1;
    const int c0   = cg * 12;
    const int ksub = wid >> 1;
    if (blockIdx.x == 0 && tid == 0) out[0] = 0.0f;

    unsigned long long acc[4][12];
    #pragma unroll
    for (int i = 0; i < 4; i++)
        #pragma unroll
        for (int m = 0; m < 12; m++) acc[i][m] = 0ull;

    unsigned asB[3] = { (unsigned)__cvta_generic_to_shared(&As[0][0]),
                        (unsigned)__cvta_generic_to_shared(&As[1][0]),
                        (unsigned)__cvta_generic_to_shared(&As[2][0]) };
    unsigned wsB[3] = { (unsigned)__cvta_generic_to_shared(&Ws[0][0]),
                        (unsigned)__cvta_generic_to_shared(&Ws[1][0]),
                        (unsigned)__cvta_generic_to_shared(&Ws[2][0]) };

    auto load_tiles = [&](int kb, int bf) {
        #pragma unroll
        for (int i = 0; i < 4; i++) {
            int idx = tid + i * 128;
            int row = idx >> 2, q = idx & 3;
            cpa16(asB[bf] + (row * 20 + q * 4) * 4,
                  enc + (size_t)(rb + row) * HH + kb + q * 4);
        }
        if (tid < 96) {
            int c = tid >> 2, q = tid & 3;
            cpa16(wsB[bf] + (c * 20 + q * 4) * 4, W + (size_t)c * HH + kb + q * 4);
        }
        asm volatile("cp.async.commit_group;");
    };

    load_tiles(kb0, 0);
    load_tiles(kb0 + 16, 1);
    int buf = 0;
    for (int ki = 0; ki < 512; ki += 16) {
        if (ki + 32 < 512) {
            load_tiles(kb0 + ki + 32, (buf + 2) % 3);
            asm volatile("cp.async.wait_group 2;");
        } else if (ki + 16 < 512) {
            asm volatile("cp.async.wait_group 1;");
        } else {
            asm volatile("cp.async.wait_group 0;");
        }
        __syncthreads();
        #pragma unroll
        for (int q = 0; q < 2; q++) {
            const int k4 = ksub * 8 + q * 4;
            ulonglong2 a[4];
            #pragma unroll
            for (int i = 0; i < 4; i++)
                a[i] = *reinterpret_cast<const ulonglong2*>(
                    &As[buf][(lane + 32 * i) * 20 + k4]);
            #pragma unroll
            for (int m = 0; m < 12; m++) {
                ulonglong2 wv = *reinterpret_cast<const ulonglong2*>(
                    &Ws[buf][(c0 + m) * 20 + k4]);
                #pragma unroll
                for (int i = 0; i < 4; i++) {
                    ffma2(acc[i][m], a[i].x, wv.x);
                    ffma2(acc[i][m], a[i].y, wv.y);
                }
            }
        }
        __syncthreads();
        buf = (buf + 1) % 3;
    }

    // reduce f32x2 -> f32 partials
    float p[48];
    #pragma unroll
    for (int i = 0; i < 4; i++)
        #pragma unroll
        for (int m = 0; m < 12; m++) {
            float2 f = *reinterpret_cast<float2*>(&acc[i][m]);
            p[i * 12 + m] = f.x + f.y;
        }

    if (ksub == 1) {
        #pragma unroll
        for (int n = 0; n < 48; n++) red[cg][lane][n] = p[n];
    }
    __syncthreads();

    if (ksub == 0) {
        float* dst = kh ? g_part1 : g_part0;
        #pragma unroll
        for (int i = 0; i < 4; i++) {
            const int r = rb + lane + 32 * i;
            #pragma unroll
            for (int m = 0; m < 12; m++) {
                int col = c0 + m;
                int kt = col >> 3, cc = col & 7;
                float val = p[i * 12 + m] + red[cg][lane][i * 12 + m]
                          + (kh ? 0.0f : bias[col]);
                dst[((size_t)kt * NROW + r) * 8 + cc] = val;
            }
        }
    }
}

// combine: logits = p0 + p1; write to out and exp to g_expo
__global__ __launch_bounds__(256) void combine_kernel(float* __restrict__ out)
{
    const int i4 = (blockIdx.x * 256 + threadIdx.x) * 4;
    float4 p0 = *reinterpret_cast<const float4*>(&g_part0[i4]);
    float4 p1 = *reinterpret_cast<const float4*>(&g_part1[i4]);
    float v0 = p0.x + p1.x, v1 = p0.y + p1.y, v2 = p0.z + p1.z, v3 = p0.w + p1.w;
    out[LOGITS_OFF + i4 + 0] = v0;
    out[LOGITS_OFF + i4 + 1] = v1;
    out[LOGITS_OFF + i4 + 2] = v2;
    out[LOGITS_OFF + i4 + 3] = v3;
    float4 e = { __expf(v0), __expf(v1), __expf(v2), __expf(v3) };
    *reinterpret_cast<float4*>(&g_expo[i4]) = e;
}

// ---------------------------------------------------------------------------
// crf: 192 blocks x 160 threads, 2 sequences per block. (unchanged from R14)
// ---------------------------------------------------------------------------
__global__ __launch_bounds__(160) void crf_kernel(
    const int* __restrict__ labels, const float* __restrict__ start_t,
    const float* __restrict__ end_t, const float* __restrict__ trans,
    float* __restrict__ out)
{
    __shared__ float         vsm[2][TT][8];
    __shared__ unsigned char path[2][8][8][64];
    __shared__ unsigned char sel[2][8];
    __shared__ float         strT[64];
    __shared__ int           lastsh[2];
    __shared__ float         Psm[2][8][8][8];
    __shared__ float         numsh[2];

    const int tid  = threadIdx.x;
    const int lane = tid & 31;

    if (blockIdx.x < 96) {
        const int s0 = blockIdx.x * 2;
        const int kt = s0 >> 6;

        if (tid < 64) strT[tid] = trans[kt * 64 + (tid & 7) * 8 + (tid >> 3)];

        if (tid < 32) {
            const int sl    = (lane >> 3) & 1;
            const int j     = lane & 7;
            const int rbase = (lane >> 4) * 4;
            const int s     = s0 + sl;
            const float* em = out + LOGITS_OFF + (size_t)s * (TT * CC);

            float tr[4];
            #pragma unroll
            for (int r = 0; r < 4; r++) tr[r] = trans[kt * 64 + (rbase + r) * 8 + j];

            float v = start_t[kt * 8 + j] + em[j];
            if (lane < 16) vsm[sl][0][j] = v;

            float eb[8];
            #pragma unroll
            for (int u = 0; u < 8; u++) eb[u] = em[(1 + u) * 8 + j];

            for (int tw = 1; tw < TT - 14; tw += 8) {
                float nb[8];
                #pragma unroll
                for (int u = 0; u < 8; u++) nb[u] = em[(tw + 8 + u) * 8 + j];
                #pragma unroll
                for (int u = 0; u < 8; u++) {
                    const int t = tw + u;
                    float c0 = __shfl_sync(FULLM, v, rbase + 0, 8) + tr[0];
                    float c1 = __shfl_sync(FULLM, v, rbase + 1, 8) + tr[1];
                    float c2 = __shfl_sync(FULLM, v, rbase + 2, 8) + tr[2];
                    float c3 = __shfl_sync(FULLM, v, rbase + 3, 8) + tr[3];
                    float pm = fmaxf(fmaxf(c0, c1), fmaxf(c2, c3));
                    float om = __shfl_xor_sync(FULLM, pm, 16, 32);
                    float m  = fmaxf(pm, om);
                    v = m + eb[u];
                    if (lane < 16) vsm[sl][t][j] = v;
                }
                #pragma unroll
                for (int u = 0; u < 8; u++) eb[u] = nb[u];
            }
            #pragma unroll
            for (int u = 0; u < 7; u++) {
                const int t = (TT - 7) + u;
                float c0 = __shfl_sync(FULLM, v, rbase + 0, 8) + tr[0];
                float c1 = __shfl_sync(FULLM, v, rbase + 1, 8) + tr[1];
                float c2 = __shfl_sync(FULLM, v, rbase + 2, 8) + tr[2];
                float c3 = __shfl_sync(FULLM, v, rbase + 3, 8) + tr[3];
                float pm = fmaxf(fmaxf(c0, c1), fmaxf(c2, c3));
                float om = __shfl_xor_sync(FULLM, pm, 16, 32);
                float m  = fmaxf(pm, om);
                v = m + eb[u];
                if (lane < 16) vsm[sl][t][j] = v;
            }

            float y = v + end_t[kt * 8 + j];
            float g[8];
            #pragma unroll
            for (int i = 0; i < 8; i++) g[i] = __shfl_sync(FULLM, y, i, 8);
            float bv = g[0]; int last = 0;
            #pragma unroll
            for (int i = 1; i < 8; i++) { if (g[i] > bv) { bv = g[i]; last = i; } }
            if (lane < 16 && j == 0) lastsh[sl] = last;
        }
        __syncthreads();

        if (tid >= 32) {
            const int did   = tid - 32;
            const int local = did >> 6;
            const int lt    = did & 63;
            const int c  = lt >> 3, h = lt & 7;
            const int tb = c * 64 + 1;
            const int te = (c * 64 + 64 < TT) ? c * 64 + 64 : TT - 1;
            int tag = h;
            for (int t = te; t >= tb; t--) {
                float4 va = *reinterpret_cast<const float4*>(&vsm[local][t - 1][0]);
                float4 vb = *reinterpret_cast<const float4*>(&vsm[local][t - 1][4]);
                const float* tc = &strT[tag * 8];
                float c0 = va.x + tc[0], c1 = va.y + tc[1];
                float c2 = va.z + tc[2], c3 = va.w + tc[3];
                float c4 = vb.x + tc[4], c5 = vb.y + tc[5];
                float c6 = vb.z + tc[6], c7 = vb.w + tc[7];
                float m = fmaxf(fmaxf(fmaxf(c0, c1), fmaxf(c2, c3)),
                                fmaxf(fmaxf(c4, c5), fmaxf(c6, c7)));
                unsigned mk = (c0 == m) ? 1u : 0u;
                mk |= (c1 == m) ? 2u : 0u;
                mk |= (c2 == m) ? 4u : 0u;
                mk |= (c3 == m) ? 8u : 0u;
                mk |= (c4 == m) ? 16u : 0u;
                mk |= (c5 == m) ? 32u : 0u;
                mk |= (c6 == m) ? 64u : 0u;
                mk |= (c7 == m) ? 128u : 0u;
                tag = __ffs(mk) - 1;
                path[local][c][h][t - tb] = (unsigned char)tag;
            }
        }
        __syncthreads();

        if (tid == 32 || tid == 96) {
            const int local = (tid - 32) >> 6;
            int ex = lastsh[local];
            for (int cc = 7; cc >= 0; cc--) {
                sel[local][cc] = (unsigned char)ex;
                ex = path[local][cc][ex][0];
            }
        }
        __syncthreads();

        if (tid >= 32) {
            const int did   = tid - 32;
            const int local = did >> 6;
            const int lt    = did & 63;
            if (lt < 8) {
                const int cc = lt;
                const int tb = cc * 64 + 1;
                const int te = (cc * 64 + 64 < TT) ? cc * 64 + 64 : TT - 1;
                const int stag = sel[local][cc];
                float* pred = out + PRED_OFF + (size_t)(s0 + local) * TT;
                pred[te] = (float)stag;
                const unsigned char* pp = &path[local][cc][stag][0];
                for (int idx = te - tb; idx >= 0; idx--)
                    pred[tb - 1 + idx] = (float)pp[idx];
            }
        }
    } else {
        const int s0 = (blockIdx.x - 96) * 2;
        const int kt = s0 >> 6;

        if (tid < 128) {
            const int ib = tid & 7;
            const int c  = (tid >> 3) & 7;
            const int sl = tid >> 6;
            const int s  = s0 + sl;

            float ec[64];
            #pragma unroll
            for (int i = 0; i < 64; i++) ec[i] = __expf(trans[kt * 64 + i]) * 0.125f;

            float P[8];
            #pragma unroll
            for (int jj = 0; jj < 8; jj++) P[jj] = (jj == ib) ? 1.0f : 0.0f;

            const int tb = c * 64 + 1;
            const int te = (c * 64 + 64 < TT) ? c * 64 + 64 : TT - 1;
            const float* eo = g_expo + (size_t)s * (TT * CC);

            float4 pa0 = *reinterpret_cast<const float4*>(eo + tb * 8);
            float4 pb0 = *reinterpret_cast<const float4*>(eo + tb * 8 + 4);
            float4 pa1 = *reinterpret_cast<const float4*>(eo + (tb + 1) * 8);
            float4 pb1 = *reinterpret_cast<const float4*>(eo + (tb + 1) * 8 + 4);

            for (int t = tb; t <= te; t++) {
                float4 ca = pa0, cb = pb0;
                pa0 = pa1; pb0 = pb1;
                int tn = t + 2;
                if (tn <= te) {
                    pa1 = *reinterpret_cast<const float4*>(eo + tn * 8);
                    pb1 = *reinterpret_cast<const float4*>(eo + tn * 8 + 4);
                }
                float np[8];
                #pragma unroll
                for (int jj = 0; jj < 8; jj++) {
                    float sum = P[0] * ec[jj];
                    #pragma unroll
                    for (int i = 1; i < 8; i++) sum = fmaf(P[i], ec[i * 8 + jj], sum);
                    np[jj] = sum;
                }
                P[0] = np[0] * ca.x; P[1] = np[1] * ca.y;
                P[2] = np[2] * ca.z; P[3] = np[3] * ca.w;
                P[4] = np[4] * cb.x; P[5] = np[5] * cb.y;
                P[6] = np[6] * cb.z; P[7] = np[7] * cb.w;
            }
            #pragma unroll
            for (int jj = 0; jj < 8; jj++) Psm[sl][c][ib][jj] = P[jj];
        } else {
            const int nid = tid - 128;
            if (nid < 16) {
                const int sl = nid >> 3, j = nid & 7;
                const int s  = s0 + sl, b = s & 63;
                const float* em = out + LOGITS_OFF + (size_t)s * (TT * CC);
                const int* lab = labels + b * (3 * TT) + kt * TT;
                float num = 0.0f;
                for (int u0 = 0; u0 < 64; u0 += 4) {
                    int tg[4], tp[4];
                    #pragma unroll
                    for (int u = 0; u < 4; u++) {
                        int t = j + 8 * (u0 + u);
                        tg[u] = lab[t];
                        tp[u] = (t > 0) ? lab[t - 1] : 0;
                    }
                    #pragma unroll
                    for (int u = 0; u < 4; u++) {
                        int t = j + 8 * (u0 + u);
                        num += em[t * 8 + tg[u]];
                        num += (t > 0) ? trans[kt * 64 + tp[u] * 8 + tg[u]]
                                       : start_t[kt * 8 + tg[u]];
                        if (t == TT - 1) num += end_t[kt * 8 + tg[u]];
                    }
                }
                #pragma unroll
                for (int d = 4; d > 0; d >>= 1) num += __shfl_xor_sync(0xFFFFu, num, d, 8);
                if (j == 0) numsh[sl] = num;
            }
        }
        __syncthreads();

        if (tid < 16) {
            const int sl = tid >> 3, j = tid & 7;
            const int s  = s0 + sl;
            const float* em = out + LOGITS_OFF + (size_t)s * (TT * CC);
            const float LOG8 = 2.0794415416798357f;

            float a = start_t[kt * 8 + j] + em[j];
            for (int c = 0; c < 8; c++) {
                float n = (c < 7) ? 64.0f : 63.0f;
                float lm[8];
                #pragma unroll
                for (int i = 0; i < 8; i++)
                    lm[i] = __logf(Psm[sl][c][i][j]) + n * LOG8 + __shfl_sync(0xFFFFu, a, i, 8);
                float m = fmaxf(fmaxf(fmaxf(lm[0], lm[1]), fmaxf(lm[2], lm[3])),
                                fmaxf(fmaxf(lm[4], lm[5]), fmaxf(lm[6], lm[7])));
                float ssum = 0.0f;
                #pragma unroll
                for (int i = 0; i < 8; i++) ssum += __expf(lm[i] - m);
                a = m + __logf(ssum);
            }
            float y = a + end_t[kt * 8 + j];
            float mm = y;
            #pragma unroll
            for (int d = 4; d > 0; d >>= 1) mm = fmaxf(mm, __shfl_xor_sync(0xFFFFu, mm, d, 8));
            float q = __expf(y - mm);
            #pragma unroll
            for (int d = 4; d > 0; d >>= 1) q += __shfl_xor_sync(0xFFFFu, q, d, 8);
            float logZ = mm + __logf(q);
            if (j == 0) atomicAdd(&out[0], logZ - numsh[sl]);
        }
    }
}

extern "C" void kernel_launch(void* const* d_in, const int* in_sizes, int n_in,
                              void* d_out, int out_size)
{
    (void)in_sizes; (void)n_in; (void)out_size;
    const float* enc     = (const float*)d_in[0];
    const int*   labels  = (const int*)  d_in[1];
    const float* W       = (const float*)d_in[2];
    const float* bias    = (const float*)d_in[3];
    const float* start_t = (const float*)d_in[4];
    const float* end_t   = (const float*)d_in[5];
    const float* trans   = (const float*)d_in[6];
    float* out = (float*)d_out;

    gemm_kernel   <<<512, 128>>>(enc, W, bias, out);
    combine_kernel<<<NLOG / 1024, 256>>>(out);
    crf_kernel    <<<192, 160>>>(labels, start_t, end_t, trans, out);
}

// round 16
// speedup vs baseline: 1.3007x; 1.1128x over previous
#include <cuda_runtime.h>

#define BB   64
#define TT   512
#define HH   1024
#define CC   8
#define NROW 32768
#define NLOG (3 * NROW * CC)
#define LOGITS_OFF 1
#define PRED_OFF   (1 + 3*BB*TT*CC)
#define FULLM 0xFFFFFFFFu

__device__ float g_expo[NLOG];    // exp(logits)

__device__ __forceinline__ void cpa16(unsigned sm, const void* g) {
    asm volatile("cp.async.cg.shared.global [%0], [%1], 16;" :: "r"(sm), "l"(g));
}
__device__ __forceinline__ unsigned tf32c(float x) {
    unsigned r;
    asm("cvt.rna.tf32.f32 %0, %1;" : "=r"(r) : "f"(x));
    return r;
}
__device__ __forceinline__ void mma8(float* c,
    unsigned a0, unsigned a1, unsigned a2, unsigned a3,
    unsigned b0, unsigned b1)
{
    asm("mma.sync.aligned.m16n8k8.row.col.f32.tf32.tf32.f32 "
        "{%0,%1,%2,%3},{%4,%5,%6,%7},{%8,%9},{%0,%1,%2,%3};"
        : "+f"(c[0]), "+f"(c[1]), "+f"(c[2]), "+f"(c[3])
        : "r"(a0), "r"(a1), "r"(a2), "r"(a3), "r"(b0), "r"(b1));
}

// ---------------------------------------------------------------------------
// GEMM via tensor cores (3xTF32): M=32768, N=24, K=1024.
// 256 blocks x 128 threads. Block tile 128 rows; warp w owns m-tiles
// {2w, 2w+1} (32 rows) x all 3 n-tiles. 3-stage cp.async k16 pipeline.
// Epilogue writes logits to out[1..] and exp(logits) to g_expo directly.
// ---------------------------------------------------------------------------
__global__ __launch_bounds__(128) void gemm_kernel(
    const float* __restrict__ enc, const float* __restrict__ W,
    const float* __restrict__ bias, float* __restrict__ out)
{
    __shared__ float As[3][128 * 20];
    __shared__ float Ws[3][24 * 20];

    const int tid  = threadIdx.x;
    const int wid  = tid >> 5;
    const int lane = tid & 31;
    const int g    = lane >> 2;      // group id 0..7
    const int tg   = lane & 3;       // thread-in-group
    const int rb   = blockIdx.x * 128;
    if (blockIdx.x == 0 && tid == 0) out[0] = 0.0f;

    float acc[2][3][4];
    #pragma unroll
    for (int mt = 0; mt < 2; mt++)
        #pragma unroll
        for (int nt = 0; nt < 3; nt++)
            #pragma unroll
            for (int q = 0; q < 4; q++) acc[mt][nt][q] = 0.0f;

    unsigned asB[3] = { (unsigned)__cvta_generic_to_shared(&As[0][0]),
                        (unsigned)__cvta_generic_to_shared(&As[1][0]),
                        (unsigned)__cvta_generic_to_shared(&As[2][0]) };
    unsigned wsB[3] = { (unsigned)__cvta_generic_to_shared(&Ws[0][0]),
                        (unsigned)__cvta_generic_to_shared(&Ws[1][0]),
                        (unsigned)__cvta_generic_to_shared(&Ws[2][0]) };

    auto load_tiles = [&](int kb, int bf) {
        #pragma unroll
        for (int i = 0; i < 4; i++) {
            int idx = tid + i * 128;
            int row = idx >> 2, q = idx & 3;
            cpa16(asB[bf] + (row * 20 + q * 4) * 4,
                  enc + (size_t)(rb + row) * HH + kb + q * 4);
        }
        if (tid < 96) {
            int c = tid >> 2, q = tid & 3;
            cpa16(wsB[bf] + (c * 20 + q * 4) * 4, W + (size_t)c * HH + kb + q * 4);
        }
        asm volatile("cp.async.commit_group;");
    };

    load_tiles(0, 0);
    load_tiles(16, 1);
    int buf = 0;
    for (int kb = 0; kb < HH; kb += 16) {
        if (kb + 32 < HH) {
            load_tiles(kb + 32, (buf + 2) % 3);
            asm volatile("cp.async.wait_group 2;");
        } else if (kb + 16 < HH) {
            asm volatile("cp.async.wait_group 1;");
        } else {
            asm volatile("cp.async.wait_group 0;");
        }
        __syncthreads();

        #pragma unroll
        for (int k8 = 0; k8 < 16; k8 += 8) {
            // --- B fragments: b0 = B[k=tg][n=g], b1 = B[k=tg+4][n=g] ---
            unsigned bb[3][2], bs[3][2];
            #pragma unroll
            for (int nt = 0; nt < 3; nt++) {
                float b0f = Ws[buf][(nt * 8 + g) * 20 + k8 + tg];
                float b1f = Ws[buf][(nt * 8 + g) * 20 + k8 + tg + 4];
                bb[nt][0] = tf32c(b0f);
                bb[nt][1] = tf32c(b1f);
                bs[nt][0] = tf32c(b0f - __uint_as_float(bb[nt][0]));
                bs[nt][1] = tf32c(b1f - __uint_as_float(bb[nt][1]));
            }
            // --- A fragments + mma ---
            #pragma unroll
            for (int mt = 0; mt < 2; mt++) {
                int row0 = (wid * 2 + mt) * 16 + g;
                float a0f = As[buf][row0 * 20 + k8 + tg];
                float a1f = As[buf][(row0 + 8) * 20 + k8 + tg];
                float a2f = As[buf][row0 * 20 + k8 + tg + 4];
                float a3f = As[buf][(row0 + 8) * 20 + k8 + tg + 4];
                unsigned ab0 = tf32c(a0f), ab1 = tf32c(a1f);
                unsigned ab2 = tf32c(a2f), ab3 = tf32c(a3f);
                unsigned as0 = tf32c(a0f - __uint_as_float(ab0));
                unsigned as1 = tf32c(a1f - __uint_as_float(ab1));
                unsigned as2 = tf32c(a2f - __uint_as_float(ab2));
                unsigned as3 = tf32c(a3f - __uint_as_float(ab3));
                #pragma unroll
                for (int nt = 0; nt < 3; nt++) {
                    mma8(acc[mt][nt], as0, as1, as2, as3, bb[nt][0], bb[nt][1]);
                    mma8(acc[mt][nt], ab0, ab1, ab2, ab3, bs[nt][0], bs[nt][1]);
                    mma8(acc[mt][nt], ab0, ab1, ab2, ab3, bb[nt][0], bb[nt][1]);
                }
            }
        }
        __syncthreads();
        buf = (buf + 1) % 3;
    }

    // epilogue: C frag (row=g [+8], col = 2*tg [+1])
    #pragma unroll
    for (int mt = 0; mt < 2; mt++) {
        const int r0 = rb + (wid * 2 + mt) * 16 + g;
        #pragma unroll
        for (int nt = 0; nt < 3; nt++) {
            const int col0 = nt * 8 + 2 * tg;          // even, col0/col0+1 same task
            const int kt = col0 >> 3, cc = col0 & 7;
            float v0 = acc[mt][nt][0] + bias[col0];
            float v1 = acc[mt][nt][1] + bias[col0 + 1];
            float v2 = acc[mt][nt][2] + bias[col0];
            float v3 = acc[mt][nt][3] + bias[col0 + 1];
            size_t b0 = ((size_t)kt * NROW + r0) * 8 + cc;
            size_t b2 = ((size_t)kt * NROW + r0 + 8) * 8 + cc;
            out[LOGITS_OFF + b0]     = v0;
            out[LOGITS_OFF + b0 + 1] = v1;
            out[LOGITS_OFF + b2]     = v2;
            out[LOGITS_OFF + b2 + 1] = v3;
            float2 e0 = { __expf(v0), __expf(v1) };
            float2 e2 = { __expf(v2), __expf(v3) };
            *reinterpret_cast<float2*>(&g_expo[b0]) = e0;
            *reinterpret_cast<float2*>(&g_expo[b2]) = e2;
        }
    }
}

// ---------------------------------------------------------------------------
// crf: 192 blocks x 160 threads, 2 sequences per block. (unchanged, validated)
// ---------------------------------------------------------------------------
__global__ __launch_bounds__(160) void crf_kernel(
    const int* __restrict__ labels, const float* __restrict__ start_t,
    const float* __restrict__ end_t, const float* __restrict__ trans,
    float* __restrict__ out)
{
    __shared__ float         vsm[2][TT][8];
    __shared__ unsigned char path[2][8][8][64];
    __shared__ unsigned char sel[2][8];
    __shared__ float         strT[64];
    __shared__ int           lastsh[2];
    __shared__ float         Psm[2][8][8][8];
    __shared__ float         numsh[2];

    const int tid  = threadIdx.x;
    const int lane = tid & 31;

    if (blockIdx.x < 96) {
        const int s0 = blockIdx.x * 2;
        const int kt = s0 >> 6;

        if (tid < 64) strT[tid] = trans[kt * 64 + (tid & 7) * 8 + (tid >> 3)];

        if (tid < 32) {
            const int sl    = (lane >> 3) & 1;
            const int j     = lane & 7;
            const int rbase = (lane >> 4) * 4;
            const int s     = s0 + sl;
            const float* em = out + LOGITS_OFF + (size_t)s * (TT * CC);

            float tr[4];
            #pragma unroll
            for (int r = 0; r < 4; r++) tr[r] = trans[kt * 64 + (rbase + r) * 8 + j];

            float v = start_t[kt * 8 + j] + em[j];
            if (lane < 16) vsm[sl][0][j] = v;

            float eb[8];
            #pragma unroll
            for (int u = 0; u < 8; u++) eb[u] = em[(1 + u) * 8 + j];

            for (int tw = 1; tw < TT - 14; tw += 8) {
                float nb[8];
                #pragma unroll
                for (int u = 0; u < 8; u++) nb[u] = em[(tw + 8 + u) * 8 + j];
                #pragma unroll
                for (int u = 0; u < 8; u++) {
                    const int t = tw + u;
                    float c0 = __shfl_sync(FULLM, v, rbase + 0, 8) + tr[0];
                    float c1 = __shfl_sync(FULLM, v, rbase + 1, 8) + tr[1];
                    float c2 = __shfl_sync(FULLM, v, rbase + 2, 8) + tr[2];
                    float c3 = __shfl_sync(FULLM, v, rbase + 3, 8) + tr[3];
                    float pm = fmaxf(fmaxf(c0, c1), fmaxf(c2, c3));
                    float om = __shfl_xor_sync(FULLM, pm, 16, 32);
                    float m  = fmaxf(pm, om);
                    v = m + eb[u];
                    if (lane < 16) vsm[sl][t][j] = v;
                }
                #pragma unroll
                for (int u = 0; u < 8; u++) eb[u] = nb[u];
            }
            #pragma unroll
            for (int u = 0; u < 7; u++) {
                const int t = (TT - 7) + u;
                float c0 = __shfl_sync(FULLM, v, rbase + 0, 8) + tr[0];
                float c1 = __shfl_sync(FULLM, v, rbase + 1, 8) + tr[1];
                float c2 = __shfl_sync(FULLM, v, rbase + 2, 8) + tr[2];
                float c3 = __shfl_sync(FULLM, v, rbase + 3, 8) + tr[3];
                float pm = fmaxf(fmaxf(c0, c1), fmaxf(c2, c3));
                float om = __shfl_xor_sync(FULLM, pm, 16, 32);
                float m  = fmaxf(pm, om);
                v = m + eb[u];
                if (lane < 16) vsm[sl][t][j] = v;
            }

            float y = v + end_t[kt * 8 + j];
            float gg[8];
            #pragma unroll
            for (int i = 0; i < 8; i++) gg[i] = __shfl_sync(FULLM, y, i, 8);
            float bv = gg[0]; int last = 0;
            #pragma unroll
            for (int i = 1; i < 8; i++) { if (gg[i] > bv) { bv = gg[i]; last = i; } }
            if (lane < 16 && j == 0) lastsh[sl] = last;
        }
        __syncthreads();

        if (tid >= 32) {
            const int did   = tid - 32;
            const int local = did >> 6;
            const int lt    = did & 63;
            const int c  = lt >> 3, h = lt & 7;
            const int tb = c * 64 + 1;
            const int te = (c * 64 + 64 < TT) ? c * 64 + 64 : TT - 1;
            int tag = h;
            for (int t = te; t >= tb; t--) {
                float4 va = *reinterpret_cast<const float4*>(&vsm[local][t - 1][0]);
                float4 vb = *reinterpret_cast<const float4*>(&vsm[local][t - 1][4]);
                const float* tc = &strT[tag * 8];
                float c0 = va.x + tc[0], c1 = va.y + tc[1];
                float c2 = va.z + tc[2], c3 = va.w + tc[3];
                float c4 = vb.x + tc[4], c5 = vb.y + tc[5];
                float c6 = vb.z + tc[6], c7 = vb.w + tc[7];
                float m = fmaxf(fmaxf(fmaxf(c0, c1), fmaxf(c2, c3)),
                                fmaxf(fmaxf(c4, c5), fmaxf(c6, c7)));
                unsigned mk = (c0 == m) ? 1u : 0u;
                mk |= (c1 == m) ? 2u : 0u;
                mk |= (c2 == m) ? 4u : 0u;
                mk |= (c3 == m) ? 8u : 0u;
                mk |= (c4 == m) ? 16u : 0u;
                mk |= (c5 == m) ? 32u : 0u;
                mk |= (c6 == m) ? 64u : 0u;
                mk |= (c7 == m) ? 128u : 0u;
                tag = __ffs(mk) - 1;
                path[local][c][h][t - tb] = (unsigned char)tag;
            }
        }
        __syncthreads();

        if (tid == 32 || tid == 96) {
            const int local = (tid - 32) >> 6;
            int ex = lastsh[local];
            for (int cc = 7; cc >= 0; cc--) {
                sel[local][cc] = (unsigned char)ex;
                ex = path[local][cc][ex][0];
            }
        }
        __syncthreads();

        if (tid >= 32) {
            const int did   = tid - 32;
            const int local = did >> 6;
            const int lt    = did & 63;
            if (lt < 8) {
                const int cc = lt;
                const int tb = cc * 64 + 1;
                const int te = (cc * 64 + 64 < TT) ? cc * 64 + 64 : TT - 1;
                const int stag = sel[local][cc];
                float* pred = out + PRED_OFF + (size_t)(s0 + local) * TT;
                pred[te] = (float)stag;
                const unsigned char* pp = &path[local][cc][stag][0];
                for (int idx = te - tb; idx >= 0; idx--)
                    pred[tb - 1 + idx] = (float)pp[idx];
            }
        }
    } else {
        const int s0 = (blockIdx.x - 96) * 2;
        const int kt = s0 >> 6;

        if (tid < 128) {
            const int ib = tid & 7;
            const int c  = (tid >> 3) & 7;
            const int sl = tid >> 6;
            const int s  = s0 + sl;

            float ec[64];
            #pragma unroll
            for (int i = 0; i < 64; i++) ec[i] = __expf(trans[kt * 64 + i]) * 0.125f;

            float P[8];
            #pragma unroll
            for (int jj = 0; jj < 8; jj++) P[jj] = (jj == ib) ? 1.0f : 0.0f;

            const int tb = c * 64 + 1;
            const int te = (c * 64 + 64 < TT) ? c * 64 + 64 : TT - 1;
            const float* eo = g_expo + (size_t)s * (TT * CC);

            float4 pa0 = *reinterpret_cast<const float4*>(eo + tb * 8);
            float4 pb0 = *reinterpret_cast<const float4*>(eo + tb * 8 + 4);
            float4 pa1 = *reinterpret_cast<const float4*>(eo + (tb + 1) * 8);
            float4 pb1 = *reinterpret_cast<const float4*>(eo + (tb + 1) * 8 + 4);

            for (int t = tb; t <= te; t++) {
                float4 ca = pa0, cb = pb0;
                pa0 = pa1; pb0 = pb1;
                int tn = t + 2;
                if (tn <= te) {
                    pa1 = *reinterpret_cast<const float4*>(eo + tn * 8);
                    pb1 = *reinterpret_cast<const float4*>(eo + tn * 8 + 4);
                }
                float np[8];
                #pragma unroll
                for (int jj = 0; jj < 8; jj++) {
                    float sum = P[0] * ec[jj];
                    #pragma unroll
                    for (int i = 1; i < 8; i++) sum = fmaf(P[i], ec[i * 8 + jj], sum);
                    np[jj] = sum;
                }
                P[0] = np[0] * ca.x; P[1] = np[1] * ca.y;
                P[2] = np[2] * ca.z; P[3] = np[3] * ca.w;
                P[4] = np[4] * cb.x; P[5] = np[5] * cb.y;
                P[6] = np[6] * cb.z; P[7] = np[7] * cb.w;
            }
            #pragma unroll
            for (int jj = 0; jj < 8; jj++) Psm[sl][c][ib][jj] = P[jj];
        } else {
            const int nid = tid - 128;
            if (nid < 16) {
                const int sl = nid >> 3, j = nid & 7;
                const int s  = s0 + sl, b = s & 63;
                const float* em = out + LOGITS_OFF + (size_t)s * (TT * CC);
                const int* lab = labels + b * (3 * TT) + kt * TT;
                float num = 0.0f;
                for (int u0 = 0; u0 < 64; u0 += 4) {
                    int tg[4], tp[4];
                    #pragma unroll
                    for (int u = 0; u < 4; u++) {
                        int t = j + 8 * (u0 + u);
                        tg[u] = lab[t];
                        tp[u] = (t > 0) ? lab[t - 1] : 0;
                    }
                    #pragma unroll
                    for (int u = 0; u < 4; u++) {
                        int t = j + 8 * (u0 + u);
                        num += em[t * 8 + tg[u]];
                        num += (t > 0) ? trans[kt * 64 + tp[u] * 8 + tg[u]]
                                       : start_t[kt * 8 + tg[u]];
                        if (t == TT - 1) num += end_t[kt * 8 + tg[u]];
                    }
                }
                #pragma unroll
                for (int d = 4; d > 0; d >>= 1) num += __shfl_xor_sync(0xFFFFu, num, d, 8);
                if (j == 0) numsh[sl] = num;
            }
        }
        __syncthreads();

        if (tid < 16) {
            const int sl = tid >> 3, j = tid & 7;
            const int s  = s0 + sl;
            const float* em = out + LOGITS_OFF + (size_t)s * (TT * CC);
            const float LOG8 = 2.0794415416798357f;

            float a = start_t[kt * 8 + j] + em[j];
            for (int c = 0; c < 8; c++) {
                float n = (c < 7) ? 64.0f : 63.0f;
                float lm[8];
                #pragma unroll
                for (int i = 0; i < 8; i++)
                    lm[i] = __logf(Psm[sl][c][i][j]) + n * LOG8 + __shfl_sync(0xFFFFu, a, i, 8);
                float m = fmaxf(fmaxf(fmaxf(lm[0], lm[1]), fmaxf(lm[2], lm[3])),
                                fmaxf(fmaxf(lm[4], lm[5]), fmaxf(lm[6], lm[7])));
                float ssum = 0.0f;
                #pragma unroll
                for (int i = 0; i < 8; i++) ssum += __expf(lm[i] - m);
                a = m + __logf(ssum);
            }
            float y = a + end_t[kt * 8 + j];
            float mm = y;
            #pragma unroll
            for (int d = 4; d > 0; d >>= 1) mm = fmaxf(mm, __shfl_xor_sync(0xFFFFu, mm, d, 8));
            float q = __expf(y - mm);
            #pragma unroll
            for (int d = 4; d > 0; d >>= 1) q += __shfl_xor_sync(0xFFFFu, q, d, 8);
            float logZ = mm + __logf(q);
            if (j == 0) atomicAdd(&out[0], logZ - numsh[sl]);
        }
    }
}

extern "C" void kernel_launch(void* const* d_in, const int* in_sizes, int n_in,
                              void* d_out, int out_size)
{
    (void)in_sizes; (void)n_in; (void)out_size;
    const float* enc     = (const float*)d_in[0];
    const int*   labels  = (const int*)  d_in[1];
    const float* W       = (const float*)d_in[2];
    const float* bias    = (const float*)d_in[3];
    const float* start_t = (const float*)d_in[4];
    const float* end_t   = (const float*)d_in[5];
    const float* trans   = (const float*)d_in[6];
    float* out = (float*)d_out;

    gemm_kernel<<<256, 128>>>(enc, W, bias, out);
    crf_kernel <<<192, 160>>>(labels, start_t, end_t, trans, out);
}